// round 11
// baseline (speedup 1.0000x reference)
#include <cuda_runtime.h>
#include <math.h>
#include <stdint.h>

#define EMB   1024
#define HS    64
#define TSEQ  4096
#define BATCH 4
#define MTOT  (BATCH * TSEQ)   // 16384 rows

#define NQT2   32              // 128-row q tiles per batch
#define CHUNK  8               // 64-row kv-tiles per partial job
#define NJOBS  144             // sum_{q=0}^{31} (q/4+1)
#define NJOBS_T (NJOBS * BATCH)

// Scratch (device globals: allocation-free rule)
__device__ float g_q[MTOT * HS];
__device__ float g_k[MTOT * HS];
__device__ float g_v[MTOT * HS];
__device__ float g_po[NJOBS_T * 128 * HS];   // partial O [slot][row][64]
__device__ float g_pm[NJOBS_T * 128];        // partial row max
__device__ float g_pl[NJOBS_T * 128];        // partial row sum

// ---- packed fp32x2 ops (Blackwell FFMA2 path; exact fp32 per lane) ----
#define FMA2(d, a, b) \
    asm("fma.rn.f32x2 %0, %1, %2, %0;" : "+l"(d) : "l"(a), "l"(b))
#define MUL2(d, a) \
    asm("mul.rn.f32x2 %0, %0, %1;" : "+l"(d) : "l"(a))
#define PACK2(d, x) \
    asm("mov.b64 %0, {%1, %1};" : "=l"(d) : "r"(__float_as_uint(x)))
#define PACKAB(d, x, y) \
    asm("mov.b64 %0, {%1, %2};" : "=l"(d) : "r"(__float_as_uint(x)), "r"(__float_as_uint(y)))
#define UNPACK2(x, y, d) do { \
    unsigned _lo, _hi; \
    asm("mov.b64 {%0, %1}, %2;" : "=r"(_lo), "=r"(_hi) : "l"(d)); \
    (x) = __uint_as_float(_lo); (y) = __uint_as_float(_hi); } while (0)

// ---------------------------------------------------------------------------
// Kernel 1: fused QKV projection. Same layouts as the measured-best version,
// but 256 threads / 4-row microtile for 2x warps (latency hiding).
// [q|k|v] = X @ [Wq|Wk|Wv]. BM=64, BN=3x64, BK=32.
// ---------------------------------------------------------------------------
#define XST 33
#define WST 68

__global__ __launch_bounds__(256, 2) void qkv_kernel(
    const float* __restrict__ X,
    const float* __restrict__ Wq,
    const float* __restrict__ Wk,
    const float* __restrict__ Wv)
{
    __shared__ __align__(16) float Xs[64 * XST];
    __shared__ __align__(16) float Ws[3][32 * WST];

    const int tid = threadIdx.x;
    const int tx = tid & 15;        // col group per W: 4*tx
    const int ty = tid >> 4;        // 0..15 -> rows 4*ty..4*ty+3
    const int m0 = blockIdx.x * 64;

    unsigned long long acc[3][4][2];
#pragma unroll
    for (int w = 0; w < 3; w++)
#pragma unroll
        for (int i = 0; i < 4; i++) { acc[w][i][0] = 0ull; acc[w][i][1] = 0ull; }

    for (int k0 = 0; k0 < EMB; k0 += 32) {
        // X tile 64x32 natural (512 float4, 2 per thread)
#pragma unroll
        for (int t = 0; t < 2; t++) {
            int idx = tid + 256 * t;
            int row = idx >> 3;            // 0..63
            int cg  = idx & 7;             // 0..7
            float4 xv = *(const float4*)&X[(size_t)(m0 + row) * EMB + k0 + 4 * cg];
            Xs[row * XST + 4 * cg + 0] = xv.x;
            Xs[row * XST + 4 * cg + 1] = xv.y;
            Xs[row * XST + 4 * cg + 2] = xv.z;
            Xs[row * XST + 4 * cg + 3] = xv.w;
        }
        // W tiles 32x64 each (512 float4 per W, 2 per thread per W)
#pragma unroll
        for (int t = 0; t < 2; t++) {
            int idx = tid + 256 * t;
            int wr = idx >> 4;             // 0..31
            int cg = idx & 15;             // 0..15
            *(float4*)&Ws[0][wr * WST + 4 * cg] =
                *(const float4*)&Wq[(size_t)(k0 + wr) * HS + 4 * cg];
            *(float4*)&Ws[1][wr * WST + 4 * cg] =
                *(const float4*)&Wk[(size_t)(k0 + wr) * HS + 4 * cg];
            *(float4*)&Ws[2][wr * WST + 4 * cg] =
                *(const float4*)&Wv[(size_t)(k0 + wr) * HS + 4 * cg];
        }
        __syncthreads();

#pragma unroll 8
        for (int kk = 0; kk < 32; kk++) {
            unsigned long long ap[4];
#pragma unroll
            for (int i = 0; i < 4; i++) {
                float a = Xs[(4 * ty + i) * XST + kk];   // broadcast scalar LDS
                PACK2(ap[i], a);
            }
            ulonglong2 b0 = *(const ulonglong2*)&Ws[0][kk * WST + 4 * tx];
            ulonglong2 b1 = *(const ulonglong2*)&Ws[1][kk * WST + 4 * tx];
            ulonglong2 b2 = *(const ulonglong2*)&Ws[2][kk * WST + 4 * tx];
#pragma unroll
            for (int i = 0; i < 4; i++) {
                FMA2(acc[0][i][0], ap[i], b0.x); FMA2(acc[0][i][1], ap[i], b0.y);
                FMA2(acc[1][i][0], ap[i], b1.x); FMA2(acc[1][i][1], ap[i], b1.y);
                FMA2(acc[2][i][0], ap[i], b2.x); FMA2(acc[2][i][1], ap[i], b2.y);
            }
        }
        __syncthreads();
    }

#pragma unroll
    for (int i = 0; i < 4; i++) {
        size_t row = (size_t)(m0 + 4 * ty + i);
        *(ulonglong2*)&g_q[row * HS + 4 * tx] = make_ulonglong2(acc[0][i][0], acc[0][i][1]);
        *(ulonglong2*)&g_k[row * HS + 4 * tx] = make_ulonglong2(acc[1][i][0], acc[1][i][1]);
        *(ulonglong2*)&g_v[row * HS + 4 * tx] = make_ulonglong2(acc[2][i][0], acc[2][i][1]);
    }
}

// ---------------------------------------------------------------------------
// Kernel 2: split-KV flash attention partials. BM=128 q-rows x 64 kv-rows.
// Same layouts/staging as R10 (measured-best), but 256 threads / 4x8
// microtile for 2x warps. Rows owned interleaved: r_i = ty + 32*i
// (ty=tid>>3, 0..31) -> warp ty-quads hit banks {0,4,8,12}+c: conflict-free.
// Cols: n = 32*(cc>>2) + 4*tx + (cc&3) matching contiguous LDS.128 b-loads.
// ---------------------------------------------------------------------------
#define QST  68    // float stride Qs/Ps rows
#define VSTR 68    // float stride Vs rows
#define SM_Q (128 * QST * 4)
#define SM_P (128 * QST * 4)
#define SM_K (64 * 64 * 4)
#define SM_V (64 * VSTR * 4)
#define ATTN_SMEM_BYTES (SM_Q + SM_P + SM_K + SM_V)   // 103424

__global__ __launch_bounds__(256, 2) void attn_partial_kernel(void)
{
    extern __shared__ __align__(16) char smbase[];
    float* Qs  = (float*)smbase;                    // [128][QST]
    float* Ps  = Qs + 128 * QST;                    // [128][QST]
    float* Kst = Ps + 128 * QST;                    // [64 h][64 j] transposed
    float* Vs  = Kst + 64 * 64;                     // [64 j][VSTR]

    const int b = blockIdx.x & 3;
    int rem = blockIdx.x >> 2;

    // decode job: q descending (LPT), nc(q) = q/4+1 chunks
    int q = 31;
    for (;;) { int nc = (q >> 2) + 1; if (rem < nc) break; rem -= nc; --q; }
    const int qt2 = q;
    const int c = rem;
    const int kt0 = CHUNK * c;
    const int kt1 = min(CHUNK * c + CHUNK, 2 * qt2 + 2);
    int pre = 0;
    for (int qq = 31; qq > qt2; --qq) pre += (qq >> 2) + 1;
    const int slot = b * NJOBS + pre + c;

    const int tid = threadIdx.x;
    const int tx = tid & 7;
    const int ty = tid >> 3;                        // 0..31 -> rows ty+32*i

    const float* Qg = g_q + ((size_t)b * TSEQ + qt2 * 128) * HS;
    const float* Kg = g_k + (size_t)b * TSEQ * HS;
    const float* Vg = g_v + (size_t)b * TSEQ * HS;

    // ---- load Q tile (128x64), plain row-major (2048 float4, 8/thread) ----
#pragma unroll
    for (int t = 0; t < 8; t++) {
        int idx = tid + 256 * t;
        int row = idx >> 4;
        int c4  = idx & 15;
        float4 v = *(const float4*)&Qg[(size_t)row * HS + 4 * c4];
        *(float4*)&Qs[row * QST + 4 * c4] = v;
    }

    float m_[4], l_[4];
    unsigned long long o2[4][4];
#pragma unroll
    for (int i = 0; i < 4; i++) {
        m_[i] = -1e30f; l_[i] = 0.0f;
#pragma unroll
        for (int jj = 0; jj < 4; jj++) o2[i][jj] = 0ull;
    }

    for (int kt = kt0; kt < kt1; kt++) {
        const float* Kt = Kg + (size_t)kt * 64 * HS;
        const float* Vt = Vg + (size_t)kt * 64 * HS;

        // ---- stage K (transposed) and V (natural) ----
        {
            int r  = tid & 63;
            int cb = tid >> 6;                      // 0..3
#pragma unroll
            for (int t = 0; t < 4; t++) {
                int c4 = cb + 4 * t;                // 0..15
                float4 kv = *(const float4*)&Kt[(size_t)r * HS + 4 * c4];
                Kst[(4 * c4 + 0) * 64 + r] = kv.x;
                Kst[(4 * c4 + 1) * 64 + r] = kv.y;
                Kst[(4 * c4 + 2) * 64 + r] = kv.z;
                Kst[(4 * c4 + 3) * 64 + r] = kv.w;
                float4 vv = *(const float4*)&Vt[(size_t)r * HS + 4 * c4];
                *(float4*)&Vs[r * VSTR + 4 * c4] = vv;
            }
        }
        __syncthreads();

        // ---- S = Q @ K^T : 4 LDS.32 + 4 MOV + 2 LDS.128 + 16 FFMA2 / h ----
        unsigned long long s2[4][4];
#pragma unroll
        for (int i = 0; i < 4; i++)
#pragma unroll
            for (int jj = 0; jj < 4; jj++) s2[i][jj] = 0ull;

#pragma unroll 8
        for (int h = 0; h < 64; h++) {
            ulonglong2 b0 = *(const ulonglong2*)&Kst[h * 64 + 4 * tx];
            ulonglong2 b1 = *(const ulonglong2*)&Kst[h * 64 + 32 + 4 * tx];
            unsigned long long ap[4];
#pragma unroll
            for (int i = 0; i < 4; i++) {
                float av = Qs[(ty + 32 * i) * QST + h];
                PACK2(ap[i], av);
            }
#pragma unroll
            for (int i = 0; i < 4; i++) {
                FMA2(s2[i][0], ap[i], b0.x); FMA2(s2[i][1], ap[i], b0.y);
                FMA2(s2[i][2], ap[i], b1.x); FMA2(s2[i][3], ap[i], b1.y);
            }
        }

        // unpack: s[i][cc], col_loc = 32*(cc>>2) + 4tx + (cc&3)
        float s[4][8];
#pragma unroll
        for (int i = 0; i < 4; i++) {
            UNPACK2(s[i][0], s[i][1], s2[i][0]);
            UNPACK2(s[i][2], s[i][3], s2[i][1]);
            UNPACK2(s[i][4], s[i][5], s2[i][2]);
            UNPACK2(s[i][6], s[i][7], s2[i][3]);
        }

        // ---- causal mask (tiles straddling/above the diagonal) ----
        if (kt >= 2 * qt2) {
            int off = (kt - 2 * qt2) * 64;
#pragma unroll
            for (int i = 0; i < 4; i++) {
                int rl = ty + 32 * i;
#pragma unroll
                for (int cc = 0; cc < 8; cc++) {
                    int cl = off + 32 * (cc >> 2) + 4 * tx + (cc & 3);
                    if (cl > rl) s[i][cc] = -1e30f;
                }
            }
        }

        // ---- online softmax (rows spread over 8 tx lanes: xor 1,2,4) ----
#pragma unroll
        for (int i = 0; i < 4; i++) {
            float mx = s[i][0];
#pragma unroll
            for (int cc = 1; cc < 8; cc++) mx = fmaxf(mx, s[i][cc]);
#pragma unroll
            for (int off = 1; off < 8; off <<= 1)
                mx = fmaxf(mx, __shfl_xor_sync(0xffffffffu, mx, off));
            float mnew = fmaxf(m_[i], mx);
            float alpha = __expf(m_[i] - mnew);
            m_[i] = mnew;
            float ps = 0.0f;
#pragma unroll
            for (int cc = 0; cc < 8; cc++) {
                s[i][cc] = __expf(s[i][cc] - mnew);
                ps += s[i][cc];
            }
#pragma unroll
            for (int off = 1; off < 8; off <<= 1)
                ps += __shfl_xor_sync(0xffffffffu, ps, off);
            l_[i] = l_[i] * alpha + ps;
            unsigned long long al2;
            PACK2(al2, alpha);
            MUL2(o2[i][0], al2); MUL2(o2[i][1], al2);
            MUL2(o2[i][2], al2); MUL2(o2[i][3], al2);
        }

        // ---- publish P (plain, u64 pair stores) ----
#pragma unroll
        for (int i = 0; i < 4; i++) {
            int row = ty + 32 * i;
#pragma unroll
            for (int jj = 0; jj < 4; jj++) {
                int n = 32 * (jj >> 1) + 4 * tx + 2 * (jj & 1);
                unsigned long long d;
                PACKAB(d, s[i][2 * jj], s[i][2 * jj + 1]);
                *(unsigned long long*)&Ps[row * QST + n] = d;
            }
        }
        __syncthreads();

        // ---- O += P @ V ----
#pragma unroll 8
        for (int j = 0; j < 64; j++) {
            ulonglong2 v0 = *(const ulonglong2*)&Vs[j * VSTR + 4 * tx];
            ulonglong2 v1 = *(const ulonglong2*)&Vs[j * VSTR + 32 + 4 * tx];
            unsigned long long pp[4];
#pragma unroll
            for (int i = 0; i < 4; i++) {
                float pv = Ps[(ty + 32 * i) * QST + j];
                PACK2(pp[i], pv);
            }
#pragma unroll
            for (int i = 0; i < 4; i++) {
                FMA2(o2[i][0], pp[i], v0.x); FMA2(o2[i][1], pp[i], v0.y);
                FMA2(o2[i][2], pp[i], v1.x); FMA2(o2[i][3], pp[i], v1.y);
            }
        }
        __syncthreads();   // PV reads done before next tile's staging
    }

    // ---- write partial (unnormalized O, row max, row sum) ----
    float* PO = g_po + (size_t)slot * 128 * HS;
#pragma unroll
    for (int i = 0; i < 4; i++) {
        int row = ty + 32 * i;
#pragma unroll
        for (int jj = 0; jj < 4; jj++) {
            int n = 32 * (jj >> 1) + 4 * tx + 2 * (jj & 1);
            *(unsigned long long*)&PO[(size_t)row * HS + n] = o2[i][jj];
        }
    }
    if (tx == 0) {
#pragma unroll
        for (int i = 0; i < 4; i++) {
            g_pm[(size_t)slot * 128 + ty + 32 * i] = m_[i];
            g_pl[(size_t)slot * 128 + ty + 32 * i] = l_[i];
        }
    }
}

// ---------------------------------------------------------------------------
// Kernel 3: combine partials (log-sum-exp merge) + epilogue /(l*8).
// Grid (32, 4), 256 thr: row = tid>>1, segment (tid&1) -> 32 cols.
// ---------------------------------------------------------------------------
__global__ __launch_bounds__(256) void attn_reduce_kernel(float* __restrict__ out)
{
    const int qt2 = blockIdx.x;
    const int b   = blockIdx.y;
    const int tid = threadIdx.x;
    const int r   = tid >> 1;
    const int n0  = (tid & 1) * 32;

    const int nc = (qt2 >> 2) + 1;
    int pre = 0;
    for (int qq = 31; qq > qt2; --qq) pre += (qq >> 2) + 1;
    const int gslot = b * NJOBS + pre;

    float m = -1e30f;
    for (int c = 0; c < nc; c++)
        m = fmaxf(m, g_pm[(size_t)(gslot + c) * 128 + r]);

    float lsum = 0.0f;
    float acc[32];
#pragma unroll
    for (int t = 0; t < 32; t++) acc[t] = 0.0f;

    for (int c = 0; c < nc; c++) {
        int slot = gslot + c;
        float w = __expf(g_pm[(size_t)slot * 128 + r] - m);
        lsum = fmaf(w, g_pl[(size_t)slot * 128 + r], lsum);
        const float* PO = g_po + ((size_t)slot * 128 + r) * HS + n0;
#pragma unroll
        for (int t = 0; t < 8; t++) {
            float4 v = *(const float4*)&PO[4 * t];
            acc[4 * t + 0] = fmaf(w, v.x, acc[4 * t + 0]);
            acc[4 * t + 1] = fmaf(w, v.y, acc[4 * t + 1]);
            acc[4 * t + 2] = fmaf(w, v.z, acc[4 * t + 2]);
            acc[4 * t + 3] = fmaf(w, v.w, acc[4 * t + 3]);
        }
    }

    // /(l) for softmax, /8 for the reference's post-softmax /sqrt(HS) quirk
    const float inv = 1.0f / (lsum * 8.0f);
    float* O = out + ((size_t)b * TSEQ + qt2 * 128 + r) * HS + n0;
#pragma unroll
    for (int t = 0; t < 8; t++) {
        float4 v = make_float4(acc[4 * t + 0] * inv, acc[4 * t + 1] * inv,
                               acc[4 * t + 2] * inv, acc[4 * t + 3] * inv);
        *(float4*)&O[4 * t] = v;
    }
}

// ---------------------------------------------------------------------------
extern "C" void kernel_launch(void* const* d_in, const int* in_sizes, int n_in,
                              void* d_out, int out_size)
{
    const float* X  = (const float*)d_in[0];
    const float* Wq = (const float*)d_in[1];
    const float* Wk = (const float*)d_in[2];
    const float* Wv = (const float*)d_in[3];
    float* out = (float*)d_out;

    (void)in_sizes; (void)n_in; (void)out_size;

    // Fused QKV projection: 256 blocks x 256 threads (13.8 warps/SM)
    qkv_kernel<<<MTOT / 64, 256>>>(X, Wq, Wk, Wv);

    // Flash attention partials: 576 blocks (batch-interleaved LPT), 256 thr
    cudaFuncSetAttribute(attn_partial_kernel,
                         cudaFuncAttributeMaxDynamicSharedMemorySize, ATTN_SMEM_BYTES);
    attn_partial_kernel<<<NJOBS_T, 256, ATTN_SMEM_BYTES>>>();

    // Combine partials + epilogue
    dim3 g3(NQT2, BATCH);
    attn_reduce_kernel<<<g3, 256>>>(out);
}

// round 12
// speedup vs baseline: 1.5417x; 1.5417x over previous
#include <cuda_runtime.h>
#include <math.h>
#include <stdint.h>

#define EMB   1024
#define HS    64
#define TSEQ  4096
#define BATCH 4
#define MTOT  (BATCH * TSEQ)   // 16384 rows

#define NQT2   32              // 128-row q tiles per batch
#define CHUNK  8               // 64-row kv-tiles per partial job
#define NJOBS  144             // sum_{q=0}^{31} (q/4+1)
#define NJOBS_T (NJOBS * BATCH)

// Scratch (device globals: allocation-free rule)
__device__ unsigned short g_qh[MTOT * HS], g_ql[MTOT * HS];   // Q hi/lo bf16, natural
__device__ unsigned short g_kh[MTOT * HS], g_kl[MTOT * HS];   // K hi/lo bf16, natural
__device__ unsigned short g_vth[BATCH * HS * TSEQ];           // V hi bf16, transposed [b][h][t]
__device__ unsigned short g_vtl[BATCH * HS * TSEQ];           // V lo
__device__ float g_po[NJOBS_T * 128 * HS];   // partial O [slot][row][64]
__device__ float g_pm[NJOBS_T * 128];        // partial row max
__device__ float g_pl[NJOBS_T * 128];        // partial row sum

// ---- packed fp32x2 ops (qkv kernel; exact fp32 per lane) ----
#define FMA2(d, a, b) \
    asm("fma.rn.f32x2 %0, %1, %2, %0;" : "+l"(d) : "l"(a), "l"(b))
#define PACK2(d, x) \
    asm("mov.b64 %0, {%1, %1};" : "=l"(d) : "r"(__float_as_uint(x)))
#define UNPACK2(x, y, d) do { \
    unsigned _lo, _hi; \
    asm("mov.b64 {%0, %1}, %2;" : "=r"(_lo), "=r"(_hi) : "l"(d)); \
    (x) = __uint_as_float(_lo); (y) = __uint_as_float(_hi); } while (0)

// ---- bf16 split helpers ----
// pack (x,y) -> bf16x2 (x in low half). PTX: cvt d, a(hi), b(lo).
__device__ __forceinline__ void split2(float x, float y, unsigned &hp, unsigned &lp) {
    asm("cvt.rn.bf16x2.f32 %0, %1, %2;" : "=r"(hp) : "f"(y), "f"(x));
    float xh = __uint_as_float(hp << 16);
    float yh = __uint_as_float(hp & 0xffff0000u);
    asm("cvt.rn.bf16x2.f32 %0, %1, %2;" : "=r"(lp) : "f"(y - yh), "f"(x - xh));
}

// ---- warp mma m16n8k16 bf16 -> f32 accumulate ----
#define MMA_BF16(c, a, b0, b1) \
    asm("mma.sync.aligned.m16n8k16.row.col.f32.bf16.bf16.f32 " \
        "{%0,%1,%2,%3},{%4,%5,%6,%7},{%8,%9},{%0,%1,%2,%3};" \
        : "+f"((c)[0]), "+f"((c)[1]), "+f"((c)[2]), "+f"((c)[3]) \
        : "r"((a)[0]), "r"((a)[1]), "r"((a)[2]), "r"((a)[3]), "r"(b0), "r"(b1))

// ---------------------------------------------------------------------------
// Kernel 1: fused QKV projection (measured-best FFMA2 core), epilogue now
// emits bf16 hi/lo: Q,K natural; V transposed [b][h][t] for the mma path.
// ---------------------------------------------------------------------------
#define XST 33
#define WST 68

__global__ __launch_bounds__(256, 2) void qkv_kernel(
    const float* __restrict__ X,
    const float* __restrict__ Wq,
    const float* __restrict__ Wk,
    const float* __restrict__ Wv)
{
    __shared__ __align__(16) float Xs[64 * XST];
    __shared__ __align__(16) float Ws[3][32 * WST];

    const int tid = threadIdx.x;
    const int tx = tid & 15;        // col group per W: 4*tx
    const int ty = tid >> 4;        // 0..15 -> rows 4*ty..4*ty+3
    const int m0 = blockIdx.x * 64;

    unsigned long long acc[3][4][2];
#pragma unroll
    for (int w = 0; w < 3; w++)
#pragma unroll
        for (int i = 0; i < 4; i++) { acc[w][i][0] = 0ull; acc[w][i][1] = 0ull; }

    for (int k0 = 0; k0 < EMB; k0 += 32) {
#pragma unroll
        for (int t = 0; t < 2; t++) {
            int idx = tid + 256 * t;
            int row = idx >> 3;
            int cg  = idx & 7;
            float4 xv = *(const float4*)&X[(size_t)(m0 + row) * EMB + k0 + 4 * cg];
            Xs[row * XST + 4 * cg + 0] = xv.x;
            Xs[row * XST + 4 * cg + 1] = xv.y;
            Xs[row * XST + 4 * cg + 2] = xv.z;
            Xs[row * XST + 4 * cg + 3] = xv.w;
        }
#pragma unroll
        for (int t = 0; t < 2; t++) {
            int idx = tid + 256 * t;
            int wr = idx >> 4;
            int cg = idx & 15;
            *(float4*)&Ws[0][wr * WST + 4 * cg] =
                *(const float4*)&Wq[(size_t)(k0 + wr) * HS + 4 * cg];
            *(float4*)&Ws[1][wr * WST + 4 * cg] =
                *(const float4*)&Wk[(size_t)(k0 + wr) * HS + 4 * cg];
            *(float4*)&Ws[2][wr * WST + 4 * cg] =
                *(const float4*)&Wv[(size_t)(k0 + wr) * HS + 4 * cg];
        }
        __syncthreads();

#pragma unroll 8
        for (int kk = 0; kk < 32; kk++) {
            unsigned long long ap[4];
#pragma unroll
            for (int i = 0; i < 4; i++) {
                float a = Xs[(4 * ty + i) * XST + kk];
                PACK2(ap[i], a);
            }
            ulonglong2 b0 = *(const ulonglong2*)&Ws[0][kk * WST + 4 * tx];
            ulonglong2 b1 = *(const ulonglong2*)&Ws[1][kk * WST + 4 * tx];
            ulonglong2 b2 = *(const ulonglong2*)&Ws[2][kk * WST + 4 * tx];
#pragma unroll
            for (int i = 0; i < 4; i++) {
                FMA2(acc[0][i][0], ap[i], b0.x); FMA2(acc[0][i][1], ap[i], b0.y);
                FMA2(acc[1][i][0], ap[i], b1.x); FMA2(acc[1][i][1], ap[i], b1.y);
                FMA2(acc[2][i][0], ap[i], b2.x); FMA2(acc[2][i][1], ap[i], b2.y);
            }
        }
        __syncthreads();
    }

    // epilogue: bf16 hi/lo split; Q,K natural u64 stores; V transposed scatter
#pragma unroll
    for (int i = 0; i < 4; i++) {
        size_t row = (size_t)(m0 + 4 * ty + i);
        int bb = (int)(row >> 12);       // batch
        int tt = (int)(row & 4095);      // position
#pragma unroll
        for (int w = 0; w < 3; w++) {
            float f0, f1, f2, f3;
            UNPACK2(f0, f1, acc[w][i][0]);
            UNPACK2(f2, f3, acc[w][i][1]);
            unsigned hp01, lp01, hp23, lp23;
            split2(f0, f1, hp01, lp01);
            split2(f2, f3, hp23, lp23);
            unsigned long long h64 = (unsigned long long)hp01 | ((unsigned long long)hp23 << 32);
            unsigned long long l64 = (unsigned long long)lp01 | ((unsigned long long)lp23 << 32);
            if (w == 0) {
                *(unsigned long long*)&g_qh[row * HS + 4 * tx] = h64;
                *(unsigned long long*)&g_ql[row * HS + 4 * tx] = l64;
            } else if (w == 1) {
                *(unsigned long long*)&g_kh[row * HS + 4 * tx] = h64;
                *(unsigned long long*)&g_kl[row * HS + 4 * tx] = l64;
            } else {
                unsigned short hv[4] = { (unsigned short)(hp01 & 0xffff), (unsigned short)(hp01 >> 16),
                                         (unsigned short)(hp23 & 0xffff), (unsigned short)(hp23 >> 16) };
                unsigned short lv[4] = { (unsigned short)(lp01 & 0xffff), (unsigned short)(lp01 >> 16),
                                         (unsigned short)(lp23 & 0xffff), (unsigned short)(lp23 >> 16) };
#pragma unroll
                for (int j = 0; j < 4; j++) {
                    size_t a = ((size_t)(bb * HS + 4 * tx + j)) * TSEQ + tt;
                    g_vth[a] = hv[j];
                    g_vtl[a] = lv[j];
                }
            }
        }
    }
}

// ---------------------------------------------------------------------------
// Kernel 2: split-KV flash attention on tensor cores (mma.sync m16n8k16,
// bf16x3 error-compensated). BM=128 q-rows x 64 kv per tile, 8 warps; warp w
// owns rows [16w,16w+16). Q frags live in regs whole kernel; P re-packed
// from S C-frags into PV A-frags in regs (no smem P). K natural / V^T smem,
// all B-frags = single conflict-free LDS.32s.
// ---------------------------------------------------------------------------
#define KST 72    // ushort stride of K/Vt smem rows
#define ATTN_SMEM_BYTES (4 * 64 * KST * 2)   // Kh,Kl,Vh,Vl = 36864

__global__ __launch_bounds__(256, 2) void attn_partial_kernel(void)
{
    extern __shared__ __align__(16) unsigned short smh[];
    unsigned short* Kh = smh;               // [64 kv][KST]  natural (h contiguous)
    unsigned short* Kl = Kh + 64 * KST;
    unsigned short* Vh = Kl + 64 * KST;     // [64 h][KST]   transposed (kv contiguous)
    unsigned short* Vl = Vh + 64 * KST;

    const int b = blockIdx.x & 3;
    int rem = blockIdx.x >> 2;
    int q = 31;
    for (;;) { int nc = (q >> 2) + 1; if (rem < nc) break; rem -= nc; --q; }
    const int qt2 = q;
    const int c = rem;
    const int kt0 = CHUNK * c;
    const int kt1 = min(CHUNK * c + CHUNK, 2 * qt2 + 2);
    int pre = 0;
    for (int qq = 31; qq > qt2; --qq) pre += (qq >> 2) + 1;
    const int slot = b * NJOBS + pre + c;

    const int tid  = threadIdx.x;
    const int w    = tid >> 5;
    const int lane = tid & 31;
    const int lq   = lane >> 2;    // 0..7
    const int lr   = lane & 3;     // 0..3

    const size_t qrow0 = (size_t)b * TSEQ + qt2 * 128 + 16 * w + lq;   // frag row
    const size_t kbase = (size_t)b * TSEQ;

    // ---- load Q fragments (hi/lo) once: rows (qrow0, qrow0+8) ----
    unsigned ah[4][4], al[4][4];
#pragma unroll
    for (int ks = 0; ks < 4; ks++) {
        int col = 2 * lr + 16 * ks;
        ah[ks][0] = *(const unsigned*)&g_qh[qrow0 * HS + col];
        ah[ks][1] = *(const unsigned*)&g_qh[(qrow0 + 8) * HS + col];
        ah[ks][2] = *(const unsigned*)&g_qh[qrow0 * HS + col + 8];
        ah[ks][3] = *(const unsigned*)&g_qh[(qrow0 + 8) * HS + col + 8];
        al[ks][0] = *(const unsigned*)&g_ql[qrow0 * HS + col];
        al[ks][1] = *(const unsigned*)&g_ql[(qrow0 + 8) * HS + col];
        al[ks][2] = *(const unsigned*)&g_ql[qrow0 * HS + col + 8];
        al[ks][3] = *(const unsigned*)&g_ql[(qrow0 + 8) * HS + col + 8];
    }

    float m0 = -1e30f, m1 = -1e30f, l0 = 0.0f, l1 = 0.0f;
    float o_[8][4];
#pragma unroll
    for (int nt = 0; nt < 8; nt++)
#pragma unroll
        for (int j = 0; j < 4; j++) o_[nt][j] = 0.0f;

    for (int kt = kt0; kt < kt1; kt++) {
        // ---- stage K (natural) and V (transposed) hi/lo tiles ----
#pragma unroll
        for (int it = 0; it < 2; it++) {
            int idx = tid + 256 * it;     // 0..511
            int row = idx >> 3;           // 0..63
            int cc  = idx & 7;            // 0..7 float4(=8 ushort) groups
            size_t kg = (kbase + (size_t)kt * 64 + row) * HS + 8 * cc;
            *(float4*)&Kh[row * KST + 8 * cc] = *(const float4*)&g_kh[kg];
            *(float4*)&Kl[row * KST + 8 * cc] = *(const float4*)&g_kl[kg];
            size_t vg = ((size_t)(b * HS + row)) * TSEQ + (size_t)kt * 64 + 8 * cc;
            *(float4*)&Vh[row * KST + 8 * cc] = *(const float4*)&g_vth[vg];
            *(float4*)&Vl[row * KST + 8 * cc] = *(const float4*)&g_vtl[vg];
        }
        __syncthreads();

        // warps 0..3 are fully masked on the above-diagonal tile: skip math
        bool active = !(kt == 2 * qt2 + 1 && w < 4);
        if (active) {
            // ---- S = Q @ K^T (bf16x3) ----
            float s[8][4];
#pragma unroll
            for (int nt = 0; nt < 8; nt++)
#pragma unroll
                for (int j = 0; j < 4; j++) s[nt][j] = 0.0f;

#pragma unroll
            for (int nt = 0; nt < 8; nt++) {
                int base = (8 * nt + lq) * KST + 2 * lr;
#pragma unroll
                for (int ks = 0; ks < 4; ks++) {
                    int o = base + 16 * ks;
                    unsigned bh0 = *(const unsigned*)&Kh[o];
                    unsigned bh1 = *(const unsigned*)&Kh[o + 8];
                    unsigned bl0 = *(const unsigned*)&Kl[o];
                    unsigned bl1 = *(const unsigned*)&Kl[o + 8];
                    MMA_BF16(s[nt], ah[ks], bh0, bh1);
                    MMA_BF16(s[nt], ah[ks], bl0, bl1);
                    MMA_BF16(s[nt], al[ks], bh0, bh1);
                }
            }

            // ---- causal mask ----
            if (kt >= 2 * qt2) {
                int off = (kt - 2 * qt2) * 64;
                int rl0 = 16 * w + lq;
                int rl1 = rl0 + 8;
#pragma unroll
                for (int nt = 0; nt < 8; nt++) {
                    int cl = off + 8 * nt + 2 * lr;
                    if (cl     > rl0) s[nt][0] = -1e30f;
                    if (cl + 1 > rl0) s[nt][1] = -1e30f;
                    if (cl     > rl1) s[nt][2] = -1e30f;
                    if (cl + 1 > rl1) s[nt][3] = -1e30f;
                }
            }

            // ---- online softmax (rows r0=16w+lq and r0+8; quad-reduce) ----
            float mx0 = -1e30f, mx1 = -1e30f;
#pragma unroll
            for (int nt = 0; nt < 8; nt++) {
                mx0 = fmaxf(mx0, fmaxf(s[nt][0], s[nt][1]));
                mx1 = fmaxf(mx1, fmaxf(s[nt][2], s[nt][3]));
            }
#pragma unroll
            for (int off = 1; off < 4; off <<= 1) {
                mx0 = fmaxf(mx0, __shfl_xor_sync(0xffffffffu, mx0, off));
                mx1 = fmaxf(mx1, __shfl_xor_sync(0xffffffffu, mx1, off));
            }
            float mn0 = fmaxf(m0, mx0), mn1 = fmaxf(m1, mx1);
            float a0 = __expf(m0 - mn0), a1 = __expf(m1 - mn1);
            m0 = mn0; m1 = mn1;
            float ps0 = 0.0f, ps1 = 0.0f;
#pragma unroll
            for (int nt = 0; nt < 8; nt++) {
                s[nt][0] = __expf(s[nt][0] - mn0); ps0 += s[nt][0];
                s[nt][1] = __expf(s[nt][1] - mn0); ps0 += s[nt][1];
                s[nt][2] = __expf(s[nt][2] - mn1); ps1 += s[nt][2];
                s[nt][3] = __expf(s[nt][3] - mn1); ps1 += s[nt][3];
            }
#pragma unroll
            for (int off = 1; off < 4; off <<= 1) {
                ps0 += __shfl_xor_sync(0xffffffffu, ps0, off);
                ps1 += __shfl_xor_sync(0xffffffffu, ps1, off);
            }
            l0 = l0 * a0 + ps0;
            l1 = l1 * a1 + ps1;
#pragma unroll
            for (int nt = 0; nt < 8; nt++) {
                o_[nt][0] *= a0; o_[nt][1] *= a0;
                o_[nt][2] *= a1; o_[nt][3] *= a1;
            }

            // ---- re-pack P (S C-frags) into PV A-frags, bf16 hi/lo ----
            unsigned ph[4][4], pl[4][4];
#pragma unroll
            for (int ks = 0; ks < 4; ks++) {
                split2(s[2 * ks][0],     s[2 * ks][1],     ph[ks][0], pl[ks][0]);
                split2(s[2 * ks][2],     s[2 * ks][3],     ph[ks][1], pl[ks][1]);
                split2(s[2 * ks + 1][0], s[2 * ks + 1][1], ph[ks][2], pl[ks][2]);
                split2(s[2 * ks + 1][2], s[2 * ks + 1][3], ph[ks][3], pl[ks][3]);
            }

            // ---- O += P @ V (bf16x3) ----
#pragma unroll
            for (int nt = 0; nt < 8; nt++) {
                int base = (8 * nt + lq) * KST + 2 * lr;
#pragma unroll
                for (int ks = 0; ks < 4; ks++) {
                    int o = base + 16 * ks;
                    unsigned bh0 = *(const unsigned*)&Vh[o];
                    unsigned bh1 = *(const unsigned*)&Vh[o + 8];
                    unsigned bl0 = *(const unsigned*)&Vl[o];
                    unsigned bl1 = *(const unsigned*)&Vl[o + 8];
                    MMA_BF16(o_[nt], ph[ks], bh0, bh1);
                    MMA_BF16(o_[nt], ph[ks], bl0, bl1);
                    MMA_BF16(o_[nt], pl[ks], bh0, bh1);
                }
            }
        }
        __syncthreads();   // tile consumed before next staging
    }

    // ---- write partial (unnormalized O, row max, row sum) ----
    float* PO = g_po + (size_t)slot * 128 * HS;
    int r0 = 16 * w + lq;
#pragma unroll
    for (int nt = 0; nt < 8; nt++) {
        int n = 8 * nt + 2 * lr;
        *(float2*)&PO[(size_t)r0 * HS + n]       = make_float2(o_[nt][0], o_[nt][1]);
        *(float2*)&PO[(size_t)(r0 + 8) * HS + n] = make_float2(o_[nt][2], o_[nt][3]);
    }
    if (lr == 0) {
        g_pm[(size_t)slot * 128 + r0]     = m0;
        g_pm[(size_t)slot * 128 + r0 + 8] = m1;
        g_pl[(size_t)slot * 128 + r0]     = l0;
        g_pl[(size_t)slot * 128 + r0 + 8] = l1;
    }
}

// ---------------------------------------------------------------------------
// Kernel 3: combine partials (log-sum-exp merge) + epilogue /(l*8).
// ---------------------------------------------------------------------------
__global__ __launch_bounds__(256) void attn_reduce_kernel(float* __restrict__ out)
{
    const int qt2 = blockIdx.x;
    const int b   = blockIdx.y;
    const int tid = threadIdx.x;
    const int r   = tid >> 1;
    const int n0  = (tid & 1) * 32;

    const int nc = (qt2 >> 2) + 1;
    int pre = 0;
    for (int qq = 31; qq > qt2; --qq) pre += (qq >> 2) + 1;
    const int gslot = b * NJOBS + pre;

    float m = -1e30f;
    for (int c = 0; c < nc; c++)
        m = fmaxf(m, g_pm[(size_t)(gslot + c) * 128 + r]);

    float lsum = 0.0f;
    float acc[32];
#pragma unroll
    for (int t = 0; t < 32; t++) acc[t] = 0.0f;

    for (int c = 0; c < nc; c++) {
        int slot = gslot + c;
        float wgt = __expf(g_pm[(size_t)slot * 128 + r] - m);
        lsum = fmaf(wgt, g_pl[(size_t)slot * 128 + r], lsum);
        const float* PO = g_po + ((size_t)slot * 128 + r) * HS + n0;
#pragma unroll
        for (int t = 0; t < 8; t++) {
            float4 v = *(const float4*)&PO[4 * t];
            acc[4 * t + 0] = fmaf(wgt, v.x, acc[4 * t + 0]);
            acc[4 * t + 1] = fmaf(wgt, v.y, acc[4 * t + 1]);
            acc[4 * t + 2] = fmaf(wgt, v.z, acc[4 * t + 2]);
            acc[4 * t + 3] = fmaf(wgt, v.w, acc[4 * t + 3]);
        }
    }

    // /(l) for softmax, /8 for the reference's post-softmax /sqrt(HS) quirk
    const float inv = 1.0f / (lsum * 8.0f);
    float* O = out + ((size_t)b * TSEQ + qt2 * 128 + r) * HS + n0;
#pragma unroll
    for (int t = 0; t < 8; t++) {
        float4 v = make_float4(acc[4 * t + 0] * inv, acc[4 * t + 1] * inv,
                               acc[4 * t + 2] * inv, acc[4 * t + 3] * inv);
        *(float4*)&O[4 * t] = v;
    }
}

// ---------------------------------------------------------------------------
extern "C" void kernel_launch(void* const* d_in, const int* in_sizes, int n_in,
                              void* d_out, int out_size)
{
    const float* X  = (const float*)d_in[0];
    const float* Wq = (const float*)d_in[1];
    const float* Wk = (const float*)d_in[2];
    const float* Wv = (const float*)d_in[3];
    float* out = (float*)d_out;

    (void)in_sizes; (void)n_in; (void)out_size;

    // Fused QKV projection + bf16 hi/lo emit
    qkv_kernel<<<MTOT / 64, 256>>>(X, Wq, Wk, Wv);

    // Flash attention partials on tensor cores
    cudaFuncSetAttribute(attn_partial_kernel,
                         cudaFuncAttributeMaxDynamicSharedMemorySize, ATTN_SMEM_BYTES);
    attn_partial_kernel<<<NJOBS_T, 256, ATTN_SMEM_BYTES>>>();

    // Combine partials + epilogue
    dim3 g3(NQT2, BATCH);
    attn_reduce_kernel<<<g3, 256>>>(out);
}

// round 13
// speedup vs baseline: 2.3647x; 1.5338x over previous
#include <cuda_runtime.h>
#include <math.h>
#include <stdint.h>

#define EMB   1024
#define HS    64
#define TSEQ  4096
#define BATCH 4
#define MTOT  (BATCH * TSEQ)   // 16384 rows

#define NQT2   32              // 128-row q tiles per batch
#define CHUNK  8               // 64-row kv-tiles per partial job
#define NJOBS  144             // sum_{q=0}^{31} (q/4+1)
#define NJOBS_T (NJOBS * BATCH)

// Scratch (device globals: allocation-free rule)
__device__ unsigned short g_qh[MTOT * HS], g_ql[MTOT * HS];   // Q hi/lo bf16, natural
__device__ unsigned short g_kh[MTOT * HS], g_kl[MTOT * HS];   // K hi/lo bf16, natural
__device__ unsigned short g_vth[BATCH * HS * TSEQ];           // V hi bf16, transposed [b][h][t]
__device__ unsigned short g_vtl[BATCH * HS * TSEQ];           // V lo
__device__ unsigned short g_wth[3 * HS * EMB];                // W hi bf16, transposed [w][n][k]
__device__ unsigned short g_wtl[3 * HS * EMB];                // W lo
__device__ float g_po[NJOBS_T * 128 * HS];   // partial O [slot][row][64]
__device__ float g_pm[NJOBS_T * 128];        // partial row max
__device__ float g_pl[NJOBS_T * 128];        // partial row sum

// ---- bf16 split helpers ----
// pack (x,y) -> bf16x2 (x in low half). PTX: cvt d, a(hi), b(lo).
__device__ __forceinline__ void split2(float x, float y, unsigned &hp, unsigned &lp) {
    asm("cvt.rn.bf16x2.f32 %0, %1, %2;" : "=r"(hp) : "f"(y), "f"(x));
    float xh = __uint_as_float(hp << 16);
    float yh = __uint_as_float(hp & 0xffff0000u);
    asm("cvt.rn.bf16x2.f32 %0, %1, %2;" : "=r"(lp) : "f"(y - yh), "f"(x - xh));
}

// ---- warp mma m16n8k16 bf16 -> f32 accumulate ----
#define MMA_BF16(c, a, b0, b1) \
    asm("mma.sync.aligned.m16n8k16.row.col.f32.bf16.bf16.f32 " \
        "{%0,%1,%2,%3},{%4,%5,%6,%7},{%8,%9},{%0,%1,%2,%3};" \
        : "+f"((c)[0]), "+f"((c)[1]), "+f"((c)[2]), "+f"((c)[3]) \
        : "r"((a)[0]), "r"((a)[1]), "r"((a)[2]), "r"((a)[3]), "r"(b0), "r"(b1))

// ---------------------------------------------------------------------------
// Kernel 0: split W into transposed bf16 hi/lo: g_wt*[w][n][k] from W[k][n].
// ---------------------------------------------------------------------------
__global__ __launch_bounds__(256) void wsplit_kernel(
    const float* __restrict__ Wq,
    const float* __restrict__ Wk,
    const float* __restrict__ Wv)
{
    int idx = blockIdx.x * 256 + threadIdx.x;     // 0 .. 3*1024*64-1
    if (idx >= 3 * EMB * HS) return;
    int w   = idx >> 16;            // 65536 elems per W
    int rem = idx & 65535;
    int k   = rem >> 6;
    int n   = rem & 63;
    const float* W = (w == 0) ? Wq : (w == 1) ? Wk : Wv;
    float x = W[k * HS + n];
    unsigned short h, l;
    asm("cvt.rn.bf16.f32 %0, %1;" : "=h"(h) : "f"(x));
    float xh = __uint_as_float(((unsigned)h) << 16);
    float xl = x - xh;
    asm("cvt.rn.bf16.f32 %0, %1;" : "=h"(l) : "f"(xl));
    g_wth[((size_t)w * HS + n) * EMB + k] = h;
    g_wtl[((size_t)w * HS + n) * EMB + k] = l;
}

// ---------------------------------------------------------------------------
// Kernel 1: fused QKV projection on tensor cores (mma m16n8k16, bf16x3).
// BM=64 rows, BK=64, N=3x64. 128 threads = 4 warps; warp owns 16 rows.
// X tile converted fp32 -> hi/lo bf16 smem on the fly; W hi/lo loaded
// pre-transposed so B-frags are conflict-free LDS.32s (bank 4*lq+lr).
// Epilogue: Q,K natural hi/lo; V transposed [b][h][t] (attn's input format).
// ---------------------------------------------------------------------------
#define XKS 72   // ushort stride of X/W smem rows
#define QKV_SMEM_BYTES ((2 * 64 * XKS + 2 * 3 * 64 * XKS) * 2)   // 73728

__global__ __launch_bounds__(128, 2) void qkv_kernel(const float* __restrict__ X)
{
    extern __shared__ __align__(16) unsigned short sm[];
    unsigned short* Xh = sm;                    // [64 m][XKS]
    unsigned short* Xl = Xh + 64 * XKS;
    unsigned short* Wh = Xl + 64 * XKS;         // [3*64 n][XKS]
    unsigned short* Wl = Wh + 3 * 64 * XKS;

    const int tid  = threadIdx.x;
    const int wid  = tid >> 5;
    const int lane = tid & 31;
    const int lq   = lane >> 2;   // 0..7
    const int lr   = lane & 3;    // 0..3
    const int m0   = blockIdx.x * 64;

    float c[3][8][4];
#pragma unroll
    for (int w3 = 0; w3 < 3; w3++)
#pragma unroll
        for (int nt = 0; nt < 8; nt++)
#pragma unroll
            for (int j = 0; j < 4; j++) c[w3][nt][j] = 0.0f;

    for (int k0 = 0; k0 < EMB; k0 += 64) {
        // ---- stage X tile 64x64: fp32 -> bf16 hi/lo ----
#pragma unroll
        for (int t = 0; t < 8; t++) {
            int idx = tid + 128 * t;          // 0..1023 float4
            int row = idx >> 4;
            int cg  = idx & 15;
            float4 v = *(const float4*)&X[(size_t)(m0 + row) * EMB + k0 + 4 * cg];
            unsigned h01, l01, h23, l23;
            split2(v.x, v.y, h01, l01);
            split2(v.z, v.w, h23, l23);
            *(unsigned*)&Xh[row * XKS + 4 * cg]     = h01;
            *(unsigned*)&Xh[row * XKS + 4 * cg + 2] = h23;
            *(unsigned*)&Xl[row * XKS + 4 * cg]     = l01;
            *(unsigned*)&Xl[row * XKS + 4 * cg + 2] = l23;
        }
        // ---- stage W tiles (pre-split bf16, transposed) ----
#pragma unroll
        for (int t = 0; t < 24; t++) {
            int idx  = tid + 128 * t;         // 0..3071 float4(=8 ushort)
            int wh   = idx >> 9;              // 0..5
            int w3   = wh >> 1;
            int half = wh & 1;
            int rem  = idx & 511;
            int n    = rem >> 3;
            int cc   = rem & 7;
            const unsigned short* src = half ? g_wtl : g_wth;
            unsigned short* dst = half ? Wl : Wh;
            *(float4*)&dst[(w3 * 64 + n) * XKS + 8 * cc] =
                *(const float4*)&src[((size_t)w3 * 64 + n) * EMB + k0 + 8 * cc];
        }
        __syncthreads();

        // ---- A fragments (hi/lo) for this chunk ----
        unsigned ah[4][4], al[4][4];
        int r = 16 * wid + lq;
#pragma unroll
        for (int ks = 0; ks < 4; ks++) {
            int col = 2 * lr + 16 * ks;
            ah[ks][0] = *(const unsigned*)&Xh[r * XKS + col];
            ah[ks][1] = *(const unsigned*)&Xh[(r + 8) * XKS + col];
            ah[ks][2] = *(const unsigned*)&Xh[r * XKS + col + 8];
            ah[ks][3] = *(const unsigned*)&Xh[(r + 8) * XKS + col + 8];
            al[ks][0] = *(const unsigned*)&Xl[r * XKS + col];
            al[ks][1] = *(const unsigned*)&Xl[(r + 8) * XKS + col];
            al[ks][2] = *(const unsigned*)&Xl[r * XKS + col + 8];
            al[ks][3] = *(const unsigned*)&Xl[(r + 8) * XKS + col + 8];
        }

        // ---- mma: 3 W x 8 n-tiles x 4 k-steps x 3 bf16x3 terms ----
#pragma unroll
        for (int w3 = 0; w3 < 3; w3++)
#pragma unroll
            for (int nt = 0; nt < 8; nt++)
#pragma unroll
                for (int ks = 0; ks < 4; ks++) {
                    int base = (w3 * 64 + 8 * nt + lq) * XKS + 2 * lr + 16 * ks;
                    unsigned bh0 = *(const unsigned*)&Wh[base];
                    unsigned bh1 = *(const unsigned*)&Wh[base + 8];
                    unsigned bl0 = *(const unsigned*)&Wl[base];
                    unsigned bl1 = *(const unsigned*)&Wl[base + 8];
                    MMA_BF16(c[w3][nt], ah[ks], bh0, bh1);
                    MMA_BF16(c[w3][nt], ah[ks], bl0, bl1);
                    MMA_BF16(c[w3][nt], al[ks], bh0, bh1);
                }
        __syncthreads();
    }

    // ---- epilogue: bf16 hi/lo; Q,K natural; V transposed scatter ----
    const int r0 = m0 + 16 * wid + lq;
    const int bb = r0 >> 12;
    const int t0 = r0 & 4095;
#pragma unroll
    for (int nt = 0; nt < 8; nt++) {
        int n0 = 8 * nt + 2 * lr;
        unsigned hp, lp;
        // Q rows r0, r0+8
        split2(c[0][nt][0], c[0][nt][1], hp, lp);
        *(unsigned*)&g_qh[(size_t)r0 * HS + n0] = hp;
        *(unsigned*)&g_ql[(size_t)r0 * HS + n0] = lp;
        split2(c[0][nt][2], c[0][nt][3], hp, lp);
        *(unsigned*)&g_qh[(size_t)(r0 + 8) * HS + n0] = hp;
        *(unsigned*)&g_ql[(size_t)(r0 + 8) * HS + n0] = lp;
        // K rows r0, r0+8
        split2(c[1][nt][0], c[1][nt][1], hp, lp);
        *(unsigned*)&g_kh[(size_t)r0 * HS + n0] = hp;
        *(unsigned*)&g_kl[(size_t)r0 * HS + n0] = lp;
        split2(c[1][nt][2], c[1][nt][3], hp, lp);
        *(unsigned*)&g_kh[(size_t)(r0 + 8) * HS + n0] = hp;
        *(unsigned*)&g_kl[(size_t)(r0 + 8) * HS + n0] = lp;
        // V transposed: [b][n][t]
        split2(c[2][nt][0], c[2][nt][1], hp, lp);
        g_vth[((size_t)bb * HS + n0) * TSEQ + t0]     = (unsigned short)hp;
        g_vth[((size_t)bb * HS + n0 + 1) * TSEQ + t0] = (unsigned short)(hp >> 16);
        g_vtl[((size_t)bb * HS + n0) * TSEQ + t0]     = (unsigned short)lp;
        g_vtl[((size_t)bb * HS + n0 + 1) * TSEQ + t0] = (unsigned short)(lp >> 16);
        split2(c[2][nt][2], c[2][nt][3], hp, lp);
        g_vth[((size_t)bb * HS + n0) * TSEQ + t0 + 8]     = (unsigned short)hp;
        g_vth[((size_t)bb * HS + n0 + 1) * TSEQ + t0 + 8] = (unsigned short)(hp >> 16);
        g_vtl[((size_t)bb * HS + n0) * TSEQ + t0 + 8]     = (unsigned short)lp;
        g_vtl[((size_t)bb * HS + n0 + 1) * TSEQ + t0 + 8] = (unsigned short)(lp >> 16);
    }
}

// ---------------------------------------------------------------------------
// Kernel 2: split-KV flash attention on tensor cores (verbatim R12 winner).
// ---------------------------------------------------------------------------
#define KST 72    // ushort stride of K/Vt smem rows
#define ATTN_SMEM_BYTES (4 * 64 * KST * 2)   // Kh,Kl,Vh,Vl = 36864

__global__ __launch_bounds__(256, 2) void attn_partial_kernel(void)
{
    extern __shared__ __align__(16) unsigned short smh[];
    unsigned short* Kh = smh;               // [64 kv][KST]  natural (h contiguous)
    unsigned short* Kl = Kh + 64 * KST;
    unsigned short* Vh = Kl + 64 * KST;     // [64 h][KST]   transposed (kv contiguous)
    unsigned short* Vl = Vh + 64 * KST;

    const int b = blockIdx.x & 3;
    int rem = blockIdx.x >> 2;
    int q = 31;
    for (;;) { int nc = (q >> 2) + 1; if (rem < nc) break; rem -= nc; --q; }
    const int qt2 = q;
    const int c = rem;
    const int kt0 = CHUNK * c;
    const int kt1 = min(CHUNK * c + CHUNK, 2 * qt2 + 2);
    int pre = 0;
    for (int qq = 31; qq > qt2; --qq) pre += (qq >> 2) + 1;
    const int slot = b * NJOBS + pre + c;

    const int tid  = threadIdx.x;
    const int w    = tid >> 5;
    const int lane = tid & 31;
    const int lq   = lane >> 2;    // 0..7
    const int lr   = lane & 3;     // 0..3

    const size_t qrow0 = (size_t)b * TSEQ + qt2 * 128 + 16 * w + lq;
    const size_t kbase = (size_t)b * TSEQ;

    // ---- load Q fragments (hi/lo) once ----
    unsigned ah[4][4], al[4][4];
#pragma unroll
    for (int ks = 0; ks < 4; ks++) {
        int col = 2 * lr + 16 * ks;
        ah[ks][0] = *(const unsigned*)&g_qh[qrow0 * HS + col];
        ah[ks][1] = *(const unsigned*)&g_qh[(qrow0 + 8) * HS + col];
        ah[ks][2] = *(const unsigned*)&g_qh[qrow0 * HS + col + 8];
        ah[ks][3] = *(const unsigned*)&g_qh[(qrow0 + 8) * HS + col + 8];
        al[ks][0] = *(const unsigned*)&g_ql[qrow0 * HS + col];
        al[ks][1] = *(const unsigned*)&g_ql[(qrow0 + 8) * HS + col];
        al[ks][2] = *(const unsigned*)&g_ql[qrow0 * HS + col + 8];
        al[ks][3] = *(const unsigned*)&g_ql[(qrow0 + 8) * HS + col + 8];
    }

    float m0 = -1e30f, m1 = -1e30f, l0 = 0.0f, l1 = 0.0f;
    float o_[8][4];
#pragma unroll
    for (int nt = 0; nt < 8; nt++)
#pragma unroll
        for (int j = 0; j < 4; j++) o_[nt][j] = 0.0f;

    for (int kt = kt0; kt < kt1; kt++) {
#pragma unroll
        for (int it = 0; it < 2; it++) {
            int idx = tid + 256 * it;
            int row = idx >> 3;
            int cc  = idx & 7;
            size_t kg = (kbase + (size_t)kt * 64 + row) * HS + 8 * cc;
            *(float4*)&Kh[row * KST + 8 * cc] = *(const float4*)&g_kh[kg];
            *(float4*)&Kl[row * KST + 8 * cc] = *(const float4*)&g_kl[kg];
            size_t vg = ((size_t)(b * HS + row)) * TSEQ + (size_t)kt * 64 + 8 * cc;
            *(float4*)&Vh[row * KST + 8 * cc] = *(const float4*)&g_vth[vg];
            *(float4*)&Vl[row * KST + 8 * cc] = *(const float4*)&g_vtl[vg];
        }
        __syncthreads();

        bool active = !(kt == 2 * qt2 + 1 && w < 4);
        if (active) {
            float s[8][4];
#pragma unroll
            for (int nt = 0; nt < 8; nt++)
#pragma unroll
                for (int j = 0; j < 4; j++) s[nt][j] = 0.0f;

#pragma unroll
            for (int nt = 0; nt < 8; nt++) {
                int base = (8 * nt + lq) * KST + 2 * lr;
#pragma unroll
                for (int ks = 0; ks < 4; ks++) {
                    int o = base + 16 * ks;
                    unsigned bh0 = *(const unsigned*)&Kh[o];
                    unsigned bh1 = *(const unsigned*)&Kh[o + 8];
                    unsigned bl0 = *(const unsigned*)&Kl[o];
                    unsigned bl1 = *(const unsigned*)&Kl[o + 8];
                    MMA_BF16(s[nt], ah[ks], bh0, bh1);
                    MMA_BF16(s[nt], ah[ks], bl0, bl1);
                    MMA_BF16(s[nt], al[ks], bh0, bh1);
                }
            }

            if (kt >= 2 * qt2) {
                int off = (kt - 2 * qt2) * 64;
                int rl0 = 16 * w + lq;
                int rl1 = rl0 + 8;
#pragma unroll
                for (int nt = 0; nt < 8; nt++) {
                    int cl = off + 8 * nt + 2 * lr;
                    if (cl     > rl0) s[nt][0] = -1e30f;
                    if (cl + 1 > rl0) s[nt][1] = -1e30f;
                    if (cl     > rl1) s[nt][2] = -1e30f;
                    if (cl + 1 > rl1) s[nt][3] = -1e30f;
                }
            }

            float mx0 = -1e30f, mx1 = -1e30f;
#pragma unroll
            for (int nt = 0; nt < 8; nt++) {
                mx0 = fmaxf(mx0, fmaxf(s[nt][0], s[nt][1]));
                mx1 = fmaxf(mx1, fmaxf(s[nt][2], s[nt][3]));
            }
#pragma unroll
            for (int off = 1; off < 4; off <<= 1) {
                mx0 = fmaxf(mx0, __shfl_xor_sync(0xffffffffu, mx0, off));
                mx1 = fmaxf(mx1, __shfl_xor_sync(0xffffffffu, mx1, off));
            }
            float mn0 = fmaxf(m0, mx0), mn1 = fmaxf(m1, mx1);
            float a0 = __expf(m0 - mn0), a1 = __expf(m1 - mn1);
            m0 = mn0; m1 = mn1;
            float ps0 = 0.0f, ps1 = 0.0f;
#pragma unroll
            for (int nt = 0; nt < 8; nt++) {
                s[nt][0] = __expf(s[nt][0] - mn0); ps0 += s[nt][0];
                s[nt][1] = __expf(s[nt][1] - mn0); ps0 += s[nt][1];
                s[nt][2] = __expf(s[nt][2] - mn1); ps1 += s[nt][2];
                s[nt][3] = __expf(s[nt][3] - mn1); ps1 += s[nt][3];
            }
#pragma unroll
            for (int off = 1; off < 4; off <<= 1) {
                ps0 += __shfl_xor_sync(0xffffffffu, ps0, off);
                ps1 += __shfl_xor_sync(0xffffffffu, ps1, off);
            }
            l0 = l0 * a0 + ps0;
            l1 = l1 * a1 + ps1;
#pragma unroll
            for (int nt = 0; nt < 8; nt++) {
                o_[nt][0] *= a0; o_[nt][1] *= a0;
                o_[nt][2] *= a1; o_[nt][3] *= a1;
            }

            unsigned ph[4][4], pl[4][4];
#pragma unroll
            for (int ks = 0; ks < 4; ks++) {
                split2(s[2 * ks][0],     s[2 * ks][1],     ph[ks][0], pl[ks][0]);
                split2(s[2 * ks][2],     s[2 * ks][3],     ph[ks][1], pl[ks][1]);
                split2(s[2 * ks + 1][0], s[2 * ks + 1][1], ph[ks][2], pl[ks][2]);
                split2(s[2 * ks + 1][2], s[2 * ks + 1][3], ph[ks][3], pl[ks][3]);
            }

#pragma unroll
            for (int nt = 0; nt < 8; nt++) {
                int base = (8 * nt + lq) * KST + 2 * lr;
#pragma unroll
                for (int ks = 0; ks < 4; ks++) {
                    int o = base + 16 * ks;
                    unsigned bh0 = *(const unsigned*)&Vh[o];
                    unsigned bh1 = *(const unsigned*)&Vh[o + 8];
                    unsigned bl0 = *(const unsigned*)&Vl[o];
                    unsigned bl1 = *(const unsigned*)&Vl[o + 8];
                    MMA_BF16(o_[nt], ph[ks], bh0, bh1);
                    MMA_BF16(o_[nt], ph[ks], bl0, bl1);
                    MMA_BF16(o_[nt], pl[ks], bh0, bh1);
                }
            }
        }
        __syncthreads();
    }

    float* PO = g_po + (size_t)slot * 128 * HS;
    int r0 = 16 * w + lq;
#pragma unroll
    for (int nt = 0; nt < 8; nt++) {
        int n = 8 * nt + 2 * lr;
        *(float2*)&PO[(size_t)r0 * HS + n]       = make_float2(o_[nt][0], o_[nt][1]);
        *(float2*)&PO[(size_t)(r0 + 8) * HS + n] = make_float2(o_[nt][2], o_[nt][3]);
    }
    if (lr == 0) {
        g_pm[(size_t)slot * 128 + r0]     = m0;
        g_pm[(size_t)slot * 128 + r0 + 8] = m1;
        g_pl[(size_t)slot * 128 + r0]     = l0;
        g_pl[(size_t)slot * 128 + r0 + 8] = l1;
    }
}

// ---------------------------------------------------------------------------
// Kernel 3: combine partials (log-sum-exp merge) + epilogue /(l*8).
// ---------------------------------------------------------------------------
__global__ __launch_bounds__(256) void attn_reduce_kernel(float* __restrict__ out)
{
    const int qt2 = blockIdx.x;
    const int b   = blockIdx.y;
    const int tid = threadIdx.x;
    const int r   = tid >> 1;
    const int n0  = (tid & 1) * 32;

    const int nc = (qt2 >> 2) + 1;
    int pre = 0;
    for (int qq = 31; qq > qt2; --qq) pre += (qq >> 2) + 1;
    const int gslot = b * NJOBS + pre;

    float m = -1e30f;
    for (int c = 0; c < nc; c++)
        m = fmaxf(m, g_pm[(size_t)(gslot + c) * 128 + r]);

    float lsum = 0.0f;
    float acc[32];
#pragma unroll
    for (int t = 0; t < 32; t++) acc[t] = 0.0f;

    for (int c = 0; c < nc; c++) {
        int slot = gslot + c;
        float wgt = __expf(g_pm[(size_t)slot * 128 + r] - m);
        lsum = fmaf(wgt, g_pl[(size_t)slot * 128 + r], lsum);
        const float* PO = g_po + ((size_t)slot * 128 + r) * HS + n0;
#pragma unroll
        for (int t = 0; t < 8; t++) {
            float4 v = *(const float4*)&PO[4 * t];
            acc[4 * t + 0] = fmaf(wgt, v.x, acc[4 * t + 0]);
            acc[4 * t + 1] = fmaf(wgt, v.y, acc[4 * t + 1]);
            acc[4 * t + 2] = fmaf(wgt, v.z, acc[4 * t + 2]);
            acc[4 * t + 3] = fmaf(wgt, v.w, acc[4 * t + 3]);
        }
    }

    // /(l) for softmax, /8 for the reference's post-softmax /sqrt(HS) quirk
    const float inv = 1.0f / (lsum * 8.0f);
    float* O = out + ((size_t)b * TSEQ + qt2 * 128 + r) * HS + n0;
#pragma unroll
    for (int t = 0; t < 8; t++) {
        float4 v = make_float4(acc[4 * t + 0] * inv, acc[4 * t + 1] * inv,
                               acc[4 * t + 2] * inv, acc[4 * t + 3] * inv);
        *(float4*)&O[4 * t] = v;
    }
}

// ---------------------------------------------------------------------------
extern "C" void kernel_launch(void* const* d_in, const int* in_sizes, int n_in,
                              void* d_out, int out_size)
{
    const float* X  = (const float*)d_in[0];
    const float* Wq = (const float*)d_in[1];
    const float* Wk = (const float*)d_in[2];
    const float* Wv = (const float*)d_in[3];
    float* out = (float*)d_out;

    (void)in_sizes; (void)n_in; (void)out_size;

    // W split+transpose to bf16 hi/lo
    wsplit_kernel<<<(3 * EMB * HS + 255) / 256, 256>>>(Wq, Wk, Wv);

    // Fused QKV projection on tensor cores
    cudaFuncSetAttribute(qkv_kernel,
                         cudaFuncAttributeMaxDynamicSharedMemorySize, QKV_SMEM_BYTES);
    qkv_kernel<<<MTOT / 64, 128, QKV_SMEM_BYTES>>>(X);

    // Flash attention partials on tensor cores
    cudaFuncSetAttribute(attn_partial_kernel,
                         cudaFuncAttributeMaxDynamicSharedMemorySize, ATTN_SMEM_BYTES);
    attn_partial_kernel<<<NJOBS_T, 256, ATTN_SMEM_BYTES>>>();

    // Combine partials + epilogue
    dim3 g3(NQT2, BATCH);
    attn_reduce_kernel<<<g3, 256>>>(out);
}